// round 1
// baseline (speedup 1.0000x reference)
#include <cuda_runtime.h>

namespace {
constexpr int Bsz  = 512;
constexpr int Tlen = 4096;
constexpr int IN   = 8;
constexpr int H    = 64;
constexpr int G    = 256;   // 4*H
constexpr int NB   = 4;     // batch elements per block
constexpr int NTHR = 256;
constexpr int NBLK = Bsz / NB;  // 128

struct Smem {
  float wih0[IN][G];      // [i][g]   transposed W_ih0
  float whh0[H][G];       // [k][g]   transposed W_hh0
  float wl1[2 * H][G];    // [k][g]   rows 0..63 = W_ih1^T, 64..127 = W_hh1^T
  float bias0[G];         // b_ih0 + b_hh0
  float bias1[G];         // b_ih1 + b_hh1
  float gates[NB][G];     // [b][g] scratch (reused for both layers)
  float hcat[2 * H][NB];  // rows 0..63 = h0, 64..127 = h1 ; [k][b] for float4 broadcast
  float xbuf[2][IN][NB];  // double-buffered x[t] slice, [i][b]
  float fcw[H];
};

__device__ __forceinline__ float tanh_fast(float x) {
  float y;
  asm("tanh.approx.f32 %0, %1;" : "=f"(y) : "f"(x));
  return y;
}
__device__ __forceinline__ float sigmoid_fast(float x) {
  return fmaf(0.5f, tanh_fast(0.5f * x), 0.5f);
}
}  // namespace

extern __shared__ float smem_f[];

__global__ __launch_bounds__(NTHR, 1) void lstm2_fused_kernel(
    const float* __restrict__ x,
    const float* __restrict__ Wih0, const float* __restrict__ Whh0,
    const float* __restrict__ bih0, const float* __restrict__ bhh0,
    const float* __restrict__ Wih1, const float* __restrict__ Whh1,
    const float* __restrict__ bih1, const float* __restrict__ bhh1,
    const float* __restrict__ fcw, const float* __restrict__ fcb,
    float* __restrict__ out) {
  Smem& s = *reinterpret_cast<Smem*>(smem_f);
  const int tid = threadIdx.x;
  const int b0  = blockIdx.x * NB;

  // ---- one-time weight staging (transposed into [k][g] layout) ----
  for (int idx = tid; idx < IN * G; idx += NTHR) {
    int i = idx >> 8, g = idx & 255;
    s.wih0[i][g] = Wih0[g * IN + i];
  }
  for (int idx = tid; idx < H * G; idx += NTHR) {
    int k = idx >> 8, g = idx & 255;
    s.whh0[k][g]    = Whh0[g * H + k];
    s.wl1[k][g]     = Wih1[g * H + k];
    s.wl1[H + k][g] = Whh1[g * H + k];
  }
  for (int g = tid; g < G; g += NTHR) {
    s.bias0[g] = bih0[g] + bhh0[g];
    s.bias1[g] = bih1[g] + bhh1[g];
  }
  if (tid < H) s.fcw[tid] = fcw[tid];
  for (int idx = tid; idx < 2 * H * NB; idx += NTHR) (&s.hcat[0][0])[idx] = 0.0f;
  if (tid < NB * IN) {  // x[t=0]
    int b = tid >> 3, i = tid & 7;
    s.xbuf[0][i][b] = x[(b0 + b) * Tlen * IN + i];
  }
  __syncthreads();

  const int g  = tid;        // gate index for matvec phases
  const int pb = tid >> 6;   // (b, j) mapping for pointwise phases
  const int pj = tid & 63;
  float c0 = 0.0f, c1 = 0.0f;  // cell state lives in registers of (pb,pj) threads
  int cur = 0;

  for (int t = 0; t < Tlen; ++t) {
    // prefetch next timestep's x slice (latency hidden behind ~2 phases of compute)
    float xn = 0.0f;
    const bool isLoader = (tid < NB * IN) && (t + 1 < Tlen);
    if (isLoader) {
      int b = tid >> 3, i = tid & 7;
      xn = __ldg(&x[((b0 + b) * Tlen + (t + 1)) * IN + i]);
    }

    // ---- phase 1: layer-0 gates.  thread g, 4 batch accumulators ----
    float a0 = s.bias0[g], a1 = a0, a2 = a0, a3 = a0;
#pragma unroll
    for (int i = 0; i < IN; ++i) {
      float  w = s.wih0[i][g];
      float4 v = *reinterpret_cast<const float4*>(&s.xbuf[cur][i][0]);
      a0 = fmaf(w, v.x, a0); a1 = fmaf(w, v.y, a1);
      a2 = fmaf(w, v.z, a2); a3 = fmaf(w, v.w, a3);
    }
#pragma unroll 16
    for (int k = 0; k < H; ++k) {
      float  w = s.whh0[k][g];
      float4 v = *reinterpret_cast<const float4*>(&s.hcat[k][0]);
      a0 = fmaf(w, v.x, a0); a1 = fmaf(w, v.y, a1);
      a2 = fmaf(w, v.z, a2); a3 = fmaf(w, v.w, a3);
    }
    s.gates[0][g] = a0; s.gates[1][g] = a1;
    s.gates[2][g] = a2; s.gates[3][g] = a3;
    __syncthreads();

    // ---- phase 2: layer-0 pointwise cell ----
    {
      float gi = sigmoid_fast(s.gates[pb][pj]);
      float gf = sigmoid_fast(s.gates[pb][H + pj]);
      float gg = tanh_fast(s.gates[pb][2 * H + pj]);
      float go = sigmoid_fast(s.gates[pb][3 * H + pj]);
      c0 = fmaf(gf, c0, gi * gg);
      s.hcat[pj][pb] = go * tanh_fast(c0);
    }
    __syncthreads();

    // ---- phase 3: layer-1 gates over [h0; h1] ----
    a0 = s.bias1[g]; a1 = a0; a2 = a0; a3 = a0;
#pragma unroll 16
    for (int k = 0; k < 2 * H; ++k) {
      float  w = s.wl1[k][g];
      float4 v = *reinterpret_cast<const float4*>(&s.hcat[k][0]);
      a0 = fmaf(w, v.x, a0); a1 = fmaf(w, v.y, a1);
      a2 = fmaf(w, v.z, a2); a3 = fmaf(w, v.w, a3);
    }
    s.gates[0][g] = a0; s.gates[1][g] = a1;
    s.gates[2][g] = a2; s.gates[3][g] = a3;
    if (isLoader) {
      int b = tid >> 3, i = tid & 7;
      s.xbuf[cur ^ 1][i][b] = xn;
    }
    __syncthreads();

    // ---- phase 4: layer-1 pointwise cell ----
    {
      float gi = sigmoid_fast(s.gates[pb][pj]);
      float gf = sigmoid_fast(s.gates[pb][H + pj]);
      float gg = tanh_fast(s.gates[pb][2 * H + pj]);
      float go = sigmoid_fast(s.gates[pb][3 * H + pj]);
      c1 = fmaf(gf, c1, gi * gg);
      s.hcat[H + pj][pb] = go * tanh_fast(c1);
    }
    __syncthreads();
    cur ^= 1;
  }

  // ---- epilogue: FC + sigmoid on last h1 (once; negligible) ----
  if (tid < NB) {
    float acc = fcb[0];
#pragma unroll 16
    for (int j = 0; j < H; ++j) acc = fmaf(s.hcat[H + j][tid], s.fcw[j], acc);
    out[b0 + tid] = 1.0f / (1.0f + __expf(-acc));
  }
}

extern "C" void kernel_launch(void* const* d_in, const int* in_sizes, int n_in,
                              void* d_out, int out_size) {
  const float* x    = (const float*)d_in[0];
  const float* Wih0 = (const float*)d_in[1];
  const float* Whh0 = (const float*)d_in[2];
  const float* bih0 = (const float*)d_in[3];
  const float* bhh0 = (const float*)d_in[4];
  const float* Wih1 = (const float*)d_in[5];
  const float* Whh1 = (const float*)d_in[6];
  const float* bih1 = (const float*)d_in[7];
  const float* bhh1 = (const float*)d_in[8];
  const float* fcw  = (const float*)d_in[9];
  const float* fcb  = (const float*)d_in[10];
  float* out = (float*)d_out;

  static_assert(sizeof(Smem) <= 220 * 1024, "smem budget");
  cudaFuncSetAttribute(lstm2_fused_kernel,
                       cudaFuncAttributeMaxDynamicSharedMemorySize,
                       (int)sizeof(Smem));
  lstm2_fused_kernel<<<NBLK, NTHR, sizeof(Smem)>>>(
      x, Wih0, Whh0, bih0, bhh0, Wih1, Whh1, bih1, bhh1, fcw, fcb, out);
}

// round 2
// speedup vs baseline: 1.7699x; 1.7699x over previous
#include <cuda_runtime.h>

namespace {
constexpr int Bsz  = 512;
constexpr int Tlen = 4096;
constexpr int IN   = 8;
constexpr int H    = 64;
constexpr int G    = 256;        // 4*H
constexpr int NB   = 4;          // batch elements per block
constexpr int NTHR = 512;        // 128 gate-pairs x 4 k-splits
constexpr int NBLK = Bsz / NB;   // 128

__device__ __forceinline__ float tanh_fast(float x) {
  float y;
  asm("tanh.approx.f32 %0, %1;" : "=f"(y) : "f"(x));
  return y;
}
__device__ __forceinline__ float sigmoid_fast(float x) {
  return fmaf(0.5f, tanh_fast(0.5f * x), 0.5f);
}

// ---- packed f32x2 helpers (Blackwell FFMA2 path) ----
__device__ __forceinline__ unsigned long long splat2(float w) {
  unsigned long long r;
  asm("mov.b64 %0, {%1, %1};" : "=l"(r) : "f"(w));
  return r;
}
__device__ __forceinline__ void ffma2(unsigned long long& acc,
                                      unsigned long long a,
                                      unsigned long long b) {
  asm("fma.rn.f32x2 %0, %1, %2, %0;" : "+l"(acc) : "l"(a), "l"(b));
}
__device__ __forceinline__ void unpack2(unsigned long long v, float& lo, float& hi) {
  asm("mov.b64 {%0, %1}, %2;" : "=f"(lo), "=f"(hi) : "l"(v));
}
}  // namespace

__global__ __launch_bounds__(NTHR, 1) void lstm2_regw_kernel(
    const float* __restrict__ x,
    const float* __restrict__ Wih0, const float* __restrict__ Whh0,
    const float* __restrict__ bih0, const float* __restrict__ bhh0,
    const float* __restrict__ Wih1, const float* __restrict__ Whh1,
    const float* __restrict__ bih1, const float* __restrict__ bhh1,
    const float* __restrict__ fcw, const float* __restrict__ fcb,
    float* __restrict__ out) {
  // ---- static shared (~29 KB) ----
  __shared__ __align__(16) float2 swx[IN][128];     // (Wih0[g][i], Wih0[g+128][i])
  __shared__ __align__(16) float  part[4][NB][G];   // k-split partial sums
  __shared__ __align__(16) float  hcat[2 * H][NB];  // h0 rows 0..63, h1 rows 64..127
  __shared__ __align__(16) float  xbuf[2][IN][NB];  // double-buffered x[t]
  __shared__ float bias0[G], bias1[G];
  __shared__ float fcw_s[H];

  const int tid = threadIdx.x;
  const int b0  = blockIdx.x * NB;
  const int gp  = tid & 127;   // gate pair base: gates gp and gp+128
  const int s   = tid >> 7;    // k-split index 0..3

  // ---- register-resident weights ----
  // layer0 recurrent: k = s*16 + kk  (kk = 0..15)
  float w1h[16], w2h[16];
  // layer1 concat [Wih1 | Whh1]: k = s*32 + kk (kk = 0..31)
  float w1l[32], w2l[32];
  {
    const int g1 = gp, g2 = gp + 128;
#pragma unroll
    for (int kk = 0; kk < 16; ++kk) {
      int k = s * 16 + kk;
      w1h[kk] = Whh0[g1 * H + k];
      w2h[kk] = Whh0[g2 * H + k];
    }
    const float* M = (s < 2) ? Wih1 : Whh1;  // k<64 vs k>=64, uniform per s
#pragma unroll
    for (int kk = 0; kk < 32; ++kk) {
      int kc = (s * 32 + kk) & 63;
      w1l[kk] = M[g1 * H + kc];
      w2l[kk] = M[g2 * H + kc];
    }
  }

  // ---- shared staging ----
  for (int idx = tid; idx < IN * 128; idx += NTHR) {
    int i = idx >> 7, gq = idx & 127;
    swx[i][gq] = make_float2(Wih0[gq * IN + i], Wih0[(gq + 128) * IN + i]);
  }
  for (int g = tid; g < G; g += NTHR) {
    bias0[g] = bih0[g] + bhh0[g];
    bias1[g] = bih1[g] + bhh1[g];
  }
  if (tid < H) fcw_s[tid] = fcw[tid];
  for (int idx = tid; idx < 2 * H * NB; idx += NTHR) (&hcat[0][0])[idx] = 0.0f;
  if (tid < NB * IN) {  // x[t=0]
    int b = tid >> 3, i = tid & 7;
    xbuf[0][i][b] = x[(b0 + b) * Tlen * IN + i];
  }
  __syncthreads();

  const int pb = (tid & 255) >> 6;  // pointwise mapping (threads 0..255)
  const int pj = tid & 63;
  float c0 = 0.0f, c1 = 0.0f;
  int cur = 0;

#pragma unroll 1
  for (int t = 0; t < Tlen; ++t) {
    // prefetch next x slice (one warp)
    float xn = 0.0f;
    const bool isLoader = (tid < NB * IN) && (t + 1 < Tlen);
    if (isLoader) {
      int b = tid >> 3, i = tid & 7;
      xn = __ldg(&x[((b0 + b) * Tlen + (t + 1)) * IN + i]);
    }

    // ================= phase 1: layer-0 gates =================
    {
      unsigned long long a1_01 = 0, a1_23 = 0, a2_01 = 0, a2_23 = 0;
#pragma unroll
      for (int ii = 0; ii < 2; ++ii) {  // x contribution, 2 i's per split
        int i = s * 2 + ii;
        float2 w = swx[i][gp];
        ulonglong2 v = *reinterpret_cast<const ulonglong2*>(&xbuf[cur][i][0]);
        unsigned long long W1 = splat2(w.x), W2 = splat2(w.y);
        ffma2(a1_01, W1, v.x); ffma2(a1_23, W1, v.y);
        ffma2(a2_01, W2, v.x); ffma2(a2_23, W2, v.y);
      }
#pragma unroll
      for (int kk = 0; kk < 16; ++kk) {  // h0 contribution
        ulonglong2 v = *reinterpret_cast<const ulonglong2*>(&hcat[s * 16 + kk][0]);
        unsigned long long W1 = splat2(w1h[kk]), W2 = splat2(w2h[kk]);
        ffma2(a1_01, W1, v.x); ffma2(a1_23, W1, v.y);
        ffma2(a2_01, W2, v.x); ffma2(a2_23, W2, v.y);
      }
      float lo, hi;
      unpack2(a1_01, lo, hi); part[s][0][gp] = lo;       part[s][1][gp] = hi;
      unpack2(a1_23, lo, hi); part[s][2][gp] = lo;       part[s][3][gp] = hi;
      unpack2(a2_01, lo, hi); part[s][0][gp + 128] = lo; part[s][1][gp + 128] = hi;
      unpack2(a2_23, lo, hi); part[s][2][gp + 128] = lo; part[s][3][gp + 128] = hi;
    }
    __syncthreads();

    // ================= phase 2: layer-0 pointwise =================
    if (tid < 256) {
      float gi = bias0[pj] + part[0][pb][pj] + part[1][pb][pj] + part[2][pb][pj] + part[3][pb][pj];
      float gf = bias0[H + pj] + part[0][pb][H + pj] + part[1][pb][H + pj] +
                 part[2][pb][H + pj] + part[3][pb][H + pj];
      float gg = bias0[2 * H + pj] + part[0][pb][2 * H + pj] + part[1][pb][2 * H + pj] +
                 part[2][pb][2 * H + pj] + part[3][pb][2 * H + pj];
      float go = bias0[3 * H + pj] + part[0][pb][3 * H + pj] + part[1][pb][3 * H + pj] +
                 part[2][pb][3 * H + pj] + part[3][pb][3 * H + pj];
      gi = sigmoid_fast(gi); gf = sigmoid_fast(gf);
      gg = tanh_fast(gg);    go = sigmoid_fast(go);
      c0 = fmaf(gf, c0, gi * gg);
      hcat[pj][pb] = go * tanh_fast(c0);
    }
    __syncthreads();

    // ================= phase 3: layer-1 gates =================
    {
      unsigned long long a1_01 = 0, a1_23 = 0, a2_01 = 0, a2_23 = 0;
#pragma unroll
      for (int kk = 0; kk < 32; ++kk) {
        ulonglong2 v = *reinterpret_cast<const ulonglong2*>(&hcat[s * 32 + kk][0]);
        unsigned long long W1 = splat2(w1l[kk]), W2 = splat2(w2l[kk]);
        ffma2(a1_01, W1, v.x); ffma2(a1_23, W1, v.y);
        ffma2(a2_01, W2, v.x); ffma2(a2_23, W2, v.y);
      }
      float lo, hi;
      unpack2(a1_01, lo, hi); part[s][0][gp] = lo;       part[s][1][gp] = hi;
      unpack2(a1_23, lo, hi); part[s][2][gp] = lo;       part[s][3][gp] = hi;
      unpack2(a2_01, lo, hi); part[s][0][gp + 128] = lo; part[s][1][gp + 128] = hi;
      unpack2(a2_23, lo, hi); part[s][2][gp + 128] = lo; part[s][3][gp + 128] = hi;
    }
    if (isLoader) {
      int b = tid >> 3, i = tid & 7;
      xbuf[cur ^ 1][i][b] = xn;
    }
    __syncthreads();

    // ================= phase 4: layer-1 pointwise =================
    if (tid < 256) {
      float gi = bias1[pj] + part[0][pb][pj] + part[1][pb][pj] + part[2][pb][pj] + part[3][pb][pj];
      float gf = bias1[H + pj] + part[0][pb][H + pj] + part[1][pb][H + pj] +
                 part[2][pb][H + pj] + part[3][pb][H + pj];
      float gg = bias1[2 * H + pj] + part[0][pb][2 * H + pj] + part[1][pb][2 * H + pj] +
                 part[2][pb][2 * H + pj] + part[3][pb][2 * H + pj];
      float go = bias1[3 * H + pj] + part[0][pb][3 * H + pj] + part[1][pb][3 * H + pj] +
                 part[2][pb][3 * H + pj] + part[3][pb][3 * H + pj];
      gi = sigmoid_fast(gi); gf = sigmoid_fast(gf);
      gg = tanh_fast(gg);    go = sigmoid_fast(go);
      c1 = fmaf(gf, c1, gi * gg);
      hcat[H + pj][pb] = go * tanh_fast(c1);
    }
    __syncthreads();
    cur ^= 1;
  }

  // ---- epilogue: FC + sigmoid on last h1 ----
  if (tid < NB) {
    float acc = fcb[0];
#pragma unroll 16
    for (int j = 0; j < H; ++j) acc = fmaf(hcat[H + j][tid], fcw_s[j], acc);
    out[b0 + tid] = 1.0f / (1.0f + __expf(-acc));
  }
}

extern "C" void kernel_launch(void* const* d_in, const int* in_sizes, int n_in,
                              void* d_out, int out_size) {
  const float* x    = (const float*)d_in[0];
  const float* Wih0 = (const float*)d_in[1];
  const float* Whh0 = (const float*)d_in[2];
  const float* bih0 = (const float*)d_in[3];
  const float* bhh0 = (const float*)d_in[4];
  const float* Wih1 = (const float*)d_in[5];
  const float* Whh1 = (const float*)d_in[6];
  const float* bih1 = (const float*)d_in[7];
  const float* bhh1 = (const float*)d_in[8];
  const float* fcw  = (const float*)d_in[9];
  const float* fcb  = (const float*)d_in[10];
  float* out = (float*)d_out;

  lstm2_regw_kernel<<<NBLK, NTHR>>>(x, Wih0, Whh0, bih0, bhh0, Wih1, Whh1,
                                    bih1, bhh1, fcw, fcb, out);
}